// round 13
// baseline (speedup 1.0000x reference)
#include <cuda_runtime.h>

#define HH 512
#define WW 512
#define NC 48
#define NP (HH*WW)
#define CPT 6    // channels per thread
#define GPP 8    // channel-groups (warps) per pixel strip
#define PXW 64   // pixels per block (32 lanes x 2 px/thread)

// ---- scratch (static device globals: allocation-free, graph-safe) ----
__device__ float g_a[NC*NP];
__device__ float g_b[NC*NP];
__device__ float g_s0[NP];
__device__ float g_s1[NP];
__device__ float g_aux[12*NP];   // 12 planar scalar coeff planes

// ---- K0: fused init. Per 64-px block: coalesced transpose v -> planar g_a
//          + s0 = logsumexp, and (threads 0-63) stencil-weight precompute. ----
__global__ void __launch_bounds__(256) k_init(const float* __restrict__ v,
                                              const float* __restrict__ Dt,
                                              const float* __restrict__ dg,
                                              const float* __restrict__ hinv) {
    __shared__ float sm[64*49];
    __shared__ float red[4][64];
    int tid = threadIdx.x;
    int p0 = blockIdx.x * 64;

    const float4* src = (const float4*)v + (size_t)blockIdx.x * 768;
    #pragma unroll
    for (int i = 0; i < 3; i++) {
        int f4 = i * 256 + tid;
        float4 t = src[f4];
        int off = f4 * 4;
        int px = off / 48;
        int ch = off % 48;
        float* d = &sm[px*49 + ch];
        d[0] = t.x; d[1] = t.y; d[2] = t.z; d[3] = t.w;
    }

    if (tid < 64) {
        int p = p0 + tid;
        int h = p >> 9, w = p & 511;
        int hm = (h - 1) & 511, hp = (h + 1) & 511;
        int wm = (w - 1) & 511, wp = (w + 1) & 511;
        #define DTA(hh,ww) Dt[(((hh)<<9)+(ww))*3+0]
        #define DTC(hh,ww) Dt[(((hh)<<9)+(ww))*3+1]
        #define DTB(hh,ww) Dt[(((hh)<<9)+(ww))*3+2]
        float a00 = DTA(h,w),  c00 = DTC(h,w),  b00 = DTB(h,w);
        float a_hm = DTA(hm,w), b_hm = DTB(hm,w);
        float a_hp = DTA(hp,w), b_hp = DTB(hp,w);
        float c_wm = DTC(h,wm), b_wm = DTB(h,wm);
        float c_wp = DTC(h,wp), b_wp = DTB(h,wp);
        float b_mm = DTB(hm,wm);
        float b_mp = DTB(hm,wp);
        float b_pm = DTB(hp,wm);
        float b_pp = DTB(hp,wp);
        #undef DTA
        #undef DTC
        #undef DTB
        float A0 = (fabsf(b_pm) - b_pm + fabsf(b00) - b00) * 0.25f;
        float A1 = (c_wm + c00 - fabsf(b_wm) - fabsf(b00)) * 0.5f;
        float A2 = (fabsf(b_mm) + b_mm + fabsf(b00) + b00) * 0.25f;
        float A3 = (a_hp + a00 - fabsf(b_hp) - fabsf(b00)) * 0.5f;
        float A4 = -(a_hp + 2.0f*a00 + a_hm) * 0.5f
                   - (fabsf(b_pm) - b_pm + fabsf(b_mm) + b_mm) * 0.25f
                   - (fabsf(b_pp) + b_pp + fabsf(b_mp) - b_mp) * 0.25f
                   + (fabsf(b_hp) + fabsf(b_hm) + fabsf(b_wp) + fabsf(b_wm) + 2.0f*fabsf(b00)) * 0.5f
                   - (c_wp + 2.0f*c00 + c_wm) * 0.5f;
        float A5 = (a_hm + a00 - fabsf(b_hm) - fabsf(b00)) * 0.5f;
        float A6 = (fabsf(b_pp) + b_pp + fabsf(b00) + b00) * 0.25f;
        float A7 = (c_wp + c00 - fabsf(b_wp) - fabsf(b00)) * 0.5f;
        float A8 = (fabsf(b_mp) - b_mp + fabsf(b00) - b00) * 0.25f;

        float inv_dg = 1.0f / dg[p];
        float mhm = (h > 0)      ? 1.0f : 0.0f;
        float mhp = (h < HH - 1) ? 1.0f : 0.0f;
        float mwm = (w > 0)      ? 1.0f : 0.0f;
        float mwp = (w < WW - 1) ? 1.0f : 0.0f;

        g_aux[0*NP+p]  = A0 * inv_dg * mhm * mwm;
        g_aux[1*NP+p]  = A1 * inv_dg * mhm;
        g_aux[2*NP+p]  = A2 * inv_dg * mhm * mwp;
        g_aux[3*NP+p]  = A3 * inv_dg * mwm;
        g_aux[4*NP+p]  = A4 * inv_dg;
        g_aux[5*NP+p]  = A5 * inv_dg * mwp;
        g_aux[6*NP+p]  = A6 * inv_dg * mhp * mwm;
        g_aux[7*NP+p]  = A7 * inv_dg * mhp;
        g_aux[8*NP+p]  = A8 * inv_dg * mhp * mwp;
        g_aux[9*NP+p]  = 0.5f * hinv[p*3+0];
        g_aux[10*NP+p] = 0.5f * hinv[p*3+1];
        g_aux[11*NP+p] =        hinv[p*3+2];
    }
    __syncthreads();

    int px = tid & 63;
    int cg = tid >> 6;
    int p  = p0 + px;
    float vv[12];
    float m = -3.402823466e38f;
    #pragma unroll
    for (int j = 0; j < 12; j++) {
        vv[j] = sm[px*49 + cg*12 + j];
        m = fmaxf(m, vv[j]);
        g_a[(size_t)(cg*12 + j)*NP + p] = vv[j];
    }
    red[cg][px] = m;
    __syncthreads();
    m = fmaxf(fmaxf(red[0][px], red[1][px]), fmaxf(red[2][px], red[3][px]));
    float es = 0.0f;
    #pragma unroll
    for (int j = 0; j < 12; j++) es += __expf(vv[j] - m);
    __syncthreads();
    red[cg][px] = es;
    __syncthreads();
    if (cg == 0) {
        float sum = red[0][px] + red[1][px] + red[2][px] + red[3][px];
        g_s0[p] = m + __logf(sum);
    }
}

// cooperative, coalesced coefficient-tile stage: 12 planes x 64 px into smem
__device__ __forceinline__ void stage_coeffs(float sC[12][64], int b0, int wbase, int tid) {
    #pragma unroll
    for (int i = 0; i < 3; i++) {
        int idx = i * 256 + tid;          // 0..767
        int k = idx >> 6;
        int j = idx & 63;
        sC[k][j] = g_aux[k*NP + b0 + wbase + j];
    }
}

// ---- K2: fused Euler step (steps 1..4); 2 horiz px x 6 ch per thread.
//          Coefficients staged in smem (once per block, coalesced). ----
__global__ void __launch_bounds__(32*GPP, 4) k_step(int ssel) {
    __shared__ float2 red0[GPP][32];
    __shared__ float2 red1[GPP][32];
    __shared__ float2 red2[GPP][32];
    __shared__ float  sC[12][64];

    int tx = threadIdx.x;
    int ty = threadIdx.y;
    int c0 = ty * CPT;
    int tid = ty * 32 + tx;

    int h  = blockIdx.x >> 3;
    int wbase = (blockIdx.x & 7) << 6;
    int w  = wbase + 2 * tx;
    int hm = (h - 1) & 511, hp = (h + 1) & 511;
    int b0 = h << 9, bm = hm << 9, bp = hp << 9;
    int wm1 = (w - 1) & 511;
    int wp2 = (w + 2) & 511;
    int pA = b0 + w;

    const float* x  = (ssel == 1) ? (const float*)g_a : (const float*)g_b;
    float* xo       = (ssel == 1) ? g_b : g_a;
    const float* si = (ssel == 1) ? (const float*)g_s0 : (const float*)g_s1;
    float* so       = (ssel == 1) ? g_s1 : g_s0;

    stage_coeffs(sC, b0, wbase, tid);

    float2 s2  = *(const float2*)&si[pA];
    float2 sp2 = *(const float2*)&si[bp + w];
    float2 sr2 = *(const float2*)&si[b0 + wp2];
    float dsxA = sp2.x - s2.x, dsxB = sp2.y - s2.y;
    float dsyA = s2.y  - s2.x, dsyB = sr2.x - s2.y;
    __syncthreads();

    int jA = 2 * tx, jB = 2 * tx + 1;
    float2 val[CPT];
    float2 cen[CPT];
    float vsumA = 0.0f, vsumB = 0.0f;
    #pragma unroll
    for (int c = 0; c < CPT; c++) {
        const float* xc = x + (size_t)(c0 + c) * NP;
        float  Lm = xc[bm + wm1], Rm = xc[bm + wp2];
        float2 Mm = *(const float2*)&xc[bm + w];
        float  L0 = xc[b0 + wm1], R0 = xc[b0 + wp2];
        float2 M0 = *(const float2*)&xc[b0 + w];
        float  Lp = xc[bp + wm1], Rp = xc[bp + wp2];
        float2 Mp = *(const float2*)&xc[bp + w];

        float accA = sC[4][jA] * M0.x;
        accA = fmaf(sC[0][jA], Lm,   accA);
        accA = fmaf(sC[1][jA], Mm.x, accA);
        accA = fmaf(sC[2][jA], Mm.y, accA);
        accA = fmaf(sC[3][jA], L0,   accA);
        accA = fmaf(sC[5][jA], M0.y, accA);
        accA = fmaf(sC[6][jA], Lp,   accA);
        accA = fmaf(sC[7][jA], Mp.x, accA);
        accA = fmaf(sC[8][jA], Mp.y, accA);
        float vxA = (Mp.x - M0.x) - dsxA;
        float vyA = (M0.y - M0.x) - dsyA;
        accA = fmaf(fmaf(sC[11][jA], vyA, sC[9][jA] * vxA), vxA, accA);
        accA = fmaf(sC[10][jA], vyA * vyA, accA);
        accA = fmaf(0.1f, M0.x, accA);

        float accB = sC[4][jB] * M0.y;
        accB = fmaf(sC[0][jB], Mm.x, accB);
        accB = fmaf(sC[1][jB], Mm.y, accB);
        accB = fmaf(sC[2][jB], Rm,   accB);
        accB = fmaf(sC[3][jB], M0.x, accB);
        accB = fmaf(sC[5][jB], R0,   accB);
        accB = fmaf(sC[6][jB], Mp.x, accB);
        accB = fmaf(sC[7][jB], Mp.y, accB);
        accB = fmaf(sC[8][jB], Rp,   accB);
        float vxB = (Mp.y - M0.y) - dsxB;
        float vyB = (R0   - M0.y) - dsyB;
        accB = fmaf(fmaf(sC[11][jB], vyB, sC[9][jB] * vxB), vxB, accB);
        accB = fmaf(sC[10][jB], vyB * vyB, accB);
        accB = fmaf(0.1f, M0.y, accB);

        val[c].x = accA; val[c].y = accB;
        cen[c] = M0;
        vsumA += accA; vsumB += accB;
    }

    red0[ty][tx].x = vsumA;
    red0[ty][tx].y = vsumB;
    __syncthreads();
    float meanA = 0.0f, meanB = 0.0f;
    #pragma unroll
    for (int g = 0; g < GPP; g++) {
        meanA += red0[g][tx].x;
        meanB += red0[g][tx].y;
    }
    meanA *= (1.0f / 48.0f);
    meanB *= (1.0f / 48.0f);

    #pragma unroll
    for (int c = 0; c < CPT; c++) {
        float tA = val[c].x - meanA;
        float tB = val[c].y - meanB;
        tA = fminf(fmaxf(tA, -1e8f), 1e8f);
        tB = fminf(fmaxf(tB, -1e8f), 1e8f);
        val[c].x = fmaf(0.2f, tA, cen[c].x);
        val[c].y = fmaf(0.2f, tB, cen[c].y);
    }

    float mA = val[0].x, mB = val[0].y;
    #pragma unroll
    for (int c = 1; c < CPT; c++) {
        mA = fmaxf(mA, val[c].x);
        mB = fmaxf(mB, val[c].y);
    }
    red1[ty][tx].x = mA;
    red1[ty][tx].y = mB;
    #pragma unroll
    for (int c = 0; c < CPT; c++)
        *(float2*)&xo[(size_t)(c0 + c) * NP + pA] = val[c];
    __syncthreads();
    mA = red1[0][tx].x; mB = red1[0][tx].y;
    #pragma unroll
    for (int g = 1; g < GPP; g++) {
        mA = fmaxf(mA, red1[g][tx].x);
        mB = fmaxf(mB, red1[g][tx].y);
    }
    float esA = 0.0f, esB = 0.0f;
    #pragma unroll
    for (int c = 0; c < CPT; c++) {
        esA += __expf(val[c].x - mA);
        esB += __expf(val[c].y - mB);
    }
    red2[ty][tx].x = esA;
    red2[ty][tx].y = esB;
    __syncthreads();
    if (ty == 0) {
        float sumA = 0.0f, sumB = 0.0f;
        #pragma unroll
        for (int g = 0; g < GPP; g++) {
            sumA += red2[g][tx].x;
            sumB += red2[g][tx].y;
        }
        float2 os;
        os.x = mA + __logf(sumA);
        os.y = mB + __logf(sumB);
        *(float2*)&so[pA] = os;
    }
}

// ---- K3: final step — same stencil, smem-staged coalesced interleaved output. ----
__global__ void __launch_bounds__(32*GPP, 3) k_last(int ssel,
                                                    float* __restrict__ out_ilv) {
    __shared__ float2 red0[GPP][32];
    __shared__ float  sC[12][64];
    __shared__ float  smo[64*49];

    int tx = threadIdx.x;
    int ty = threadIdx.y;
    int c0 = ty * CPT;
    int tid = ty * 32 + tx;

    int h  = blockIdx.x >> 3;
    int wbase = (blockIdx.x & 7) << 6;
    int w  = wbase + 2 * tx;
    int hm = (h - 1) & 511, hp = (h + 1) & 511;
    int b0 = h << 9, bm = hm << 9, bp = hp << 9;
    int wm1 = (w - 1) & 511;
    int wp2 = (w + 2) & 511;
    int pA = b0 + w;

    const float* x  = (ssel == 1) ? (const float*)g_a : (const float*)g_b;
    const float* si = (ssel == 1) ? (const float*)g_s0 : (const float*)g_s1;

    stage_coeffs(sC, b0, wbase, tid);

    float2 s2  = *(const float2*)&si[pA];
    float2 sp2 = *(const float2*)&si[bp + w];
    float2 sr2 = *(const float2*)&si[b0 + wp2];
    float dsxA = sp2.x - s2.x, dsxB = sp2.y - s2.y;
    float dsyA = s2.y  - s2.x, dsyB = sr2.x - s2.y;
    __syncthreads();

    int jA = 2 * tx, jB = 2 * tx + 1;
    float2 val[CPT];
    float2 cen[CPT];
    float vsumA = 0.0f, vsumB = 0.0f;
    #pragma unroll
    for (int c = 0; c < CPT; c++) {
        const float* xc = x + (size_t)(c0 + c) * NP;
        float  Lm = xc[bm + wm1], Rm = xc[bm + wp2];
        float2 Mm = *(const float2*)&xc[bm + w];
        float  L0 = xc[b0 + wm1], R0 = xc[b0 + wp2];
        float2 M0 = *(const float2*)&xc[b0 + w];
        float  Lp = xc[bp + wm1], Rp = xc[bp + wp2];
        float2 Mp = *(const float2*)&xc[bp + w];

        float accA = sC[4][jA] * M0.x;
        accA = fmaf(sC[0][jA], Lm,   accA);
        accA = fmaf(sC[1][jA], Mm.x, accA);
        accA = fmaf(sC[2][jA], Mm.y, accA);
        accA = fmaf(sC[3][jA], L0,   accA);
        accA = fmaf(sC[5][jA], M0.y, accA);
        accA = fmaf(sC[6][jA], Lp,   accA);
        accA = fmaf(sC[7][jA], Mp.x, accA);
        accA = fmaf(sC[8][jA], Mp.y, accA);
        float vxA = (Mp.x - M0.x) - dsxA;
        float vyA = (M0.y - M0.x) - dsyA;
        accA = fmaf(fmaf(sC[11][jA], vyA, sC[9][jA] * vxA), vxA, accA);
        accA = fmaf(sC[10][jA], vyA * vyA, accA);
        accA = fmaf(0.1f, M0.x, accA);

        float accB = sC[4][jB] * M0.y;
        accB = fmaf(sC[0][jB], Mm.x, accB);
        accB = fmaf(sC[1][jB], Mm.y, accB);
        accB = fmaf(sC[2][jB], Rm,   accB);
        accB = fmaf(sC[3][jB], M0.x, accB);
        accB = fmaf(sC[5][jB], R0,   accB);
        accB = fmaf(sC[6][jB], Mp.x, accB);
        accB = fmaf(sC[7][jB], Mp.y, accB);
        accB = fmaf(sC[8][jB], Rp,   accB);
        float vxB = (Mp.y - M0.y) - dsxB;
        float vyB = (R0   - M0.y) - dsyB;
        accB = fmaf(fmaf(sC[11][jB], vyB, sC[9][jB] * vxB), vxB, accB);
        accB = fmaf(sC[10][jB], vyB * vyB, accB);
        accB = fmaf(0.1f, M0.y, accB);

        val[c].x = accA; val[c].y = accB;
        cen[c] = M0;
        vsumA += accA; vsumB += accB;
    }

    red0[ty][tx].x = vsumA;
    red0[ty][tx].y = vsumB;
    __syncthreads();
    float meanA = 0.0f, meanB = 0.0f;
    #pragma unroll
    for (int g = 0; g < GPP; g++) {
        meanA += red0[g][tx].x;
        meanB += red0[g][tx].y;
    }
    meanA *= (1.0f / 48.0f);
    meanB *= (1.0f / 48.0f);

    int pxA = 2 * tx, pxB = 2 * tx + 1;
    #pragma unroll
    for (int c = 0; c < CPT; c++) {
        float tA = val[c].x - meanA;
        float tB = val[c].y - meanB;
        tA = fminf(fmaxf(tA, -1e8f), 1e8f);
        tB = fminf(fmaxf(tB, -1e8f), 1e8f);
        smo[pxA*49 + c0 + c] = fmaf(0.2f, tA, cen[c].x);
        smo[pxB*49 + c0 + c] = fmaf(0.2f, tB, cen[c].y);
    }
    __syncthreads();

    float4* o4 = (float4*)(out_ilv + (size_t)blockIdx.x * 64 * NC);
    #pragma unroll
    for (int i = 0; i < 3; i++) {
        int f4 = i * 256 + tid;
        int off = f4 * 4;
        int px = off / 48;
        int ch = off % 48;
        const float* s4 = &smo[px*49 + ch];
        float4 t;
        t.x = s4[0]; t.y = s4[1]; t.z = s4[2]; t.w = s4[3];
        o4[f4] = t;
    }
}

extern "C" void kernel_launch(void* const* d_in, const int* in_sizes, int n_in,
                              void* d_out, int out_size) {
    const float* v    = (const float*)d_in[0];
    const float* Dt   = (const float*)d_in[1];
    const float* dg   = (const float*)d_in[2];
    const float* hinv = (const float*)d_in[3];
    float* out = (float*)d_out;

    k_init<<<NP / 64, 256>>>(v, Dt, dg, hinv);

    dim3 blk(32, GPP);
    int grid = NP / PXW;   // 4096
    k_step<<<grid, blk>>>(1);
    k_step<<<grid, blk>>>(2);
    k_step<<<grid, blk>>>(1);
    k_step<<<grid, blk>>>(2);
    k_last<<<grid, blk>>>(1, out);
}

// round 14
// speedup vs baseline: 1.3771x; 1.3771x over previous
#include <cuda_runtime.h>

#define HH 512
#define WW 512
#define NC 48
#define NP (HH*WW)
#define CPT 6    // channels per thread
#define GPP 8    // channel-groups (warps) per pixel strip
#define PXW 64   // pixels per block (32 lanes x 2 px/thread)

// ---- scratch (static device globals: allocation-free, graph-safe) ----
__device__ float g_a[NC*NP];
__device__ float g_b[NC*NP];
__device__ float g_s0[NP];
__device__ float g_s1[NP];
__device__ float g_aux[12*NP];   // 12 planar scalar coeff planes

// ---- K0: fused init. Per 64-px block: coalesced transpose v -> planar g_a
//          + s0 = logsumexp, and (threads 0-63) stencil-weight precompute. ----
__global__ void __launch_bounds__(256) k_init(const float* __restrict__ v,
                                              const float* __restrict__ Dt,
                                              const float* __restrict__ dg,
                                              const float* __restrict__ hinv) {
    __shared__ float sm[64*49];
    __shared__ float red[4][64];
    int tid = threadIdx.x;
    int p0 = blockIdx.x * 64;

    const float4* src = (const float4*)v + (size_t)blockIdx.x * 768;
    #pragma unroll
    for (int i = 0; i < 3; i++) {
        int f4 = i * 256 + tid;
        float4 t = src[f4];
        int off = f4 * 4;
        int px = off / 48;
        int ch = off % 48;
        float* d = &sm[px*49 + ch];
        d[0] = t.x; d[1] = t.y; d[2] = t.z; d[3] = t.w;
    }

    if (tid < 64) {
        int p = p0 + tid;
        int h = p >> 9, w = p & 511;
        int hm = (h - 1) & 511, hp = (h + 1) & 511;
        int wm = (w - 1) & 511, wp = (w + 1) & 511;
        #define DTA(hh,ww) Dt[(((hh)<<9)+(ww))*3+0]
        #define DTC(hh,ww) Dt[(((hh)<<9)+(ww))*3+1]
        #define DTB(hh,ww) Dt[(((hh)<<9)+(ww))*3+2]
        float a00 = DTA(h,w),  c00 = DTC(h,w),  b00 = DTB(h,w);
        float a_hm = DTA(hm,w), b_hm = DTB(hm,w);
        float a_hp = DTA(hp,w), b_hp = DTB(hp,w);
        float c_wm = DTC(h,wm), b_wm = DTB(h,wm);
        float c_wp = DTC(h,wp), b_wp = DTB(h,wp);
        float b_mm = DTB(hm,wm);
        float b_mp = DTB(hm,wp);
        float b_pm = DTB(hp,wm);
        float b_pp = DTB(hp,wp);
        #undef DTA
        #undef DTC
        #undef DTB
        float A0 = (fabsf(b_pm) - b_pm + fabsf(b00) - b00) * 0.25f;
        float A1 = (c_wm + c00 - fabsf(b_wm) - fabsf(b00)) * 0.5f;
        float A2 = (fabsf(b_mm) + b_mm + fabsf(b00) + b00) * 0.25f;
        float A3 = (a_hp + a00 - fabsf(b_hp) - fabsf(b00)) * 0.5f;
        float A4 = -(a_hp + 2.0f*a00 + a_hm) * 0.5f
                   - (fabsf(b_pm) - b_pm + fabsf(b_mm) + b_mm) * 0.25f
                   - (fabsf(b_pp) + b_pp + fabsf(b_mp) - b_mp) * 0.25f
                   + (fabsf(b_hp) + fabsf(b_hm) + fabsf(b_wp) + fabsf(b_wm) + 2.0f*fabsf(b00)) * 0.5f
                   - (c_wp + 2.0f*c00 + c_wm) * 0.5f;
        float A5 = (a_hm + a00 - fabsf(b_hm) - fabsf(b00)) * 0.5f;
        float A6 = (fabsf(b_pp) + b_pp + fabsf(b00) + b00) * 0.25f;
        float A7 = (c_wp + c00 - fabsf(b_wp) - fabsf(b00)) * 0.5f;
        float A8 = (fabsf(b_mp) - b_mp + fabsf(b00) - b00) * 0.25f;

        float inv_dg = 1.0f / dg[p];
        float mhm = (h > 0)      ? 1.0f : 0.0f;
        float mhp = (h < HH - 1) ? 1.0f : 0.0f;
        float mwm = (w > 0)      ? 1.0f : 0.0f;
        float mwp = (w < WW - 1) ? 1.0f : 0.0f;

        g_aux[0*NP+p]  = A0 * inv_dg * mhm * mwm;
        g_aux[1*NP+p]  = A1 * inv_dg * mhm;
        g_aux[2*NP+p]  = A2 * inv_dg * mhm * mwp;
        g_aux[3*NP+p]  = A3 * inv_dg * mwm;
        g_aux[4*NP+p]  = A4 * inv_dg;
        g_aux[5*NP+p]  = A5 * inv_dg * mwp;
        g_aux[6*NP+p]  = A6 * inv_dg * mhp * mwm;
        g_aux[7*NP+p]  = A7 * inv_dg * mhp;
        g_aux[8*NP+p]  = A8 * inv_dg * mhp * mwp;
        g_aux[9*NP+p]  = 0.5f * hinv[p*3+0];
        g_aux[10*NP+p] = 0.5f * hinv[p*3+1];
        g_aux[11*NP+p] =        hinv[p*3+2];
    }
    __syncthreads();

    int px = tid & 63;
    int cg = tid >> 6;
    int p  = p0 + px;
    float vv[12];
    float m = -3.402823466e38f;
    #pragma unroll
    for (int j = 0; j < 12; j++) {
        vv[j] = sm[px*49 + cg*12 + j];
        m = fmaxf(m, vv[j]);
        g_a[(size_t)(cg*12 + j)*NP + p] = vv[j];
    }
    red[cg][px] = m;
    __syncthreads();
    m = fmaxf(fmaxf(red[0][px], red[1][px]), fmaxf(red[2][px], red[3][px]));
    float es = 0.0f;
    #pragma unroll
    for (int j = 0; j < 12; j++) es += __expf(vv[j] - m);
    __syncthreads();
    red[cg][px] = es;
    __syncthreads();
    if (cg == 0) {
        float sum = red[0][px] + red[1][px] + red[2][px] + red[3][px];
        g_s0[p] = m + __logf(sum);
    }
}

// cooperative, coalesced coefficient-tile stage: 12 planes x 64 px into smem
__device__ __forceinline__ void stage_coeffs(float2 sC[12][32], int b0, int wbase, int tid) {
    float* s = (float*)sC;
    #pragma unroll
    for (int i = 0; i < 3; i++) {
        int idx = i * 256 + tid;          // 0..767
        int k = idx >> 6;
        int j = idx & 63;
        s[k*64 + j] = g_aux[k*NP + b0 + wbase + j];
    }
}

// ---- K2: fused Euler step (steps 1..4); 2 horiz px x 6 ch per thread.
//          R12 hot loop (register coefficients); coeffs staged via smem once. ----
__global__ void __launch_bounds__(32*GPP, 3) k_step(int ssel) {
    __shared__ float2 red0[GPP][32];
    __shared__ float2 red1[GPP][32];
    __shared__ float2 red2[GPP][32];
    __shared__ float2 sC[12][32];

    int tx = threadIdx.x;
    int ty = threadIdx.y;
    int c0 = ty * CPT;
    int tid = ty * 32 + tx;

    int h  = blockIdx.x >> 3;
    int wbase = (blockIdx.x & 7) << 6;
    int w  = wbase + 2 * tx;
    int hm = (h - 1) & 511, hp = (h + 1) & 511;
    int b0 = h << 9, bm = hm << 9, bp = hp << 9;
    int wm1 = (w - 1) & 511;
    int wp2 = (w + 2) & 511;
    int pA = b0 + w;

    const float* x  = (ssel == 1) ? (const float*)g_a : (const float*)g_b;
    float* xo       = (ssel == 1) ? g_b : g_a;
    const float* si = (ssel == 1) ? (const float*)g_s0 : (const float*)g_s1;
    float* so       = (ssel == 1) ? g_s1 : g_s0;

    stage_coeffs(sC, b0, wbase, tid);

    float2 s2  = *(const float2*)&si[pA];
    float2 sp2 = *(const float2*)&si[bp + w];
    float2 sr2 = *(const float2*)&si[b0 + wp2];
    float dsxA = sp2.x - s2.x, dsxB = sp2.y - s2.y;
    float dsyA = s2.y  - s2.x, dsyB = sr2.x - s2.y;
    __syncthreads();

    // one-time copy into registers: hot loop identical to R12
    float2 C[12];
    #pragma unroll
    for (int k = 0; k < 12; k++)
        C[k] = sC[k][tx];

    float2 val[CPT];
    float2 cen[CPT];
    float vsumA = 0.0f, vsumB = 0.0f;
    #pragma unroll
    for (int c = 0; c < CPT; c++) {
        const float* xc = x + (size_t)(c0 + c) * NP;
        float  Lm = xc[bm + wm1], Rm = xc[bm + wp2];
        float2 Mm = *(const float2*)&xc[bm + w];
        float  L0 = xc[b0 + wm1], R0 = xc[b0 + wp2];
        float2 M0 = *(const float2*)&xc[b0 + w];
        float  Lp = xc[bp + wm1], Rp = xc[bp + wp2];
        float2 Mp = *(const float2*)&xc[bp + w];

        float accA = C[4].x * M0.x;
        accA = fmaf(C[0].x, Lm,   accA);
        accA = fmaf(C[1].x, Mm.x, accA);
        accA = fmaf(C[2].x, Mm.y, accA);
        accA = fmaf(C[3].x, L0,   accA);
        accA = fmaf(C[5].x, M0.y, accA);
        accA = fmaf(C[6].x, Lp,   accA);
        accA = fmaf(C[7].x, Mp.x, accA);
        accA = fmaf(C[8].x, Mp.y, accA);
        float vxA = (Mp.x - M0.x) - dsxA;
        float vyA = (M0.y - M0.x) - dsyA;
        accA = fmaf(fmaf(C[11].x, vyA, C[9].x * vxA), vxA, accA);
        accA = fmaf(C[10].x, vyA * vyA, accA);
        accA = fmaf(0.1f, M0.x, accA);

        float accB = C[4].y * M0.y;
        accB = fmaf(C[0].y, Mm.x, accB);
        accB = fmaf(C[1].y, Mm.y, accB);
        accB = fmaf(C[2].y, Rm,   accB);
        accB = fmaf(C[3].y, M0.x, accB);
        accB = fmaf(C[5].y, R0,   accB);
        accB = fmaf(C[6].y, Mp.x, accB);
        accB = fmaf(C[7].y, Mp.y, accB);
        accB = fmaf(C[8].y, Rp,   accB);
        float vxB = (Mp.y - M0.y) - dsxB;
        float vyB = (R0   - M0.y) - dsyB;
        accB = fmaf(fmaf(C[11].y, vyB, C[9].y * vxB), vxB, accB);
        accB = fmaf(C[10].y, vyB * vyB, accB);
        accB = fmaf(0.1f, M0.y, accB);

        val[c].x = accA; val[c].y = accB;
        cen[c] = M0;
        vsumA += accA; vsumB += accB;
    }

    red0[ty][tx].x = vsumA;
    red0[ty][tx].y = vsumB;
    __syncthreads();
    float meanA = 0.0f, meanB = 0.0f;
    #pragma unroll
    for (int g = 0; g < GPP; g++) {
        meanA += red0[g][tx].x;
        meanB += red0[g][tx].y;
    }
    meanA *= (1.0f / 48.0f);
    meanB *= (1.0f / 48.0f);

    #pragma unroll
    for (int c = 0; c < CPT; c++) {
        float tA = val[c].x - meanA;
        float tB = val[c].y - meanB;
        tA = fminf(fmaxf(tA, -1e8f), 1e8f);
        tB = fminf(fmaxf(tB, -1e8f), 1e8f);
        val[c].x = fmaf(0.2f, tA, cen[c].x);
        val[c].y = fmaf(0.2f, tB, cen[c].y);
    }

    float mA = val[0].x, mB = val[0].y;
    #pragma unroll
    for (int c = 1; c < CPT; c++) {
        mA = fmaxf(mA, val[c].x);
        mB = fmaxf(mB, val[c].y);
    }
    red1[ty][tx].x = mA;
    red1[ty][tx].y = mB;
    #pragma unroll
    for (int c = 0; c < CPT; c++)
        *(float2*)&xo[(size_t)(c0 + c) * NP + pA] = val[c];
    __syncthreads();
    mA = red1[0][tx].x; mB = red1[0][tx].y;
    #pragma unroll
    for (int g = 1; g < GPP; g++) {
        mA = fmaxf(mA, red1[g][tx].x);
        mB = fmaxf(mB, red1[g][tx].y);
    }
    float esA = 0.0f, esB = 0.0f;
    #pragma unroll
    for (int c = 0; c < CPT; c++) {
        esA += __expf(val[c].x - mA);
        esB += __expf(val[c].y - mB);
    }
    red2[ty][tx].x = esA;
    red2[ty][tx].y = esB;
    __syncthreads();
    if (ty == 0) {
        float sumA = 0.0f, sumB = 0.0f;
        #pragma unroll
        for (int g = 0; g < GPP; g++) {
            sumA += red2[g][tx].x;
            sumB += red2[g][tx].y;
        }
        float2 os;
        os.x = mA + __logf(sumA);
        os.y = mB + __logf(sumB);
        *(float2*)&so[pA] = os;
    }
}

// ---- K3: final step — same stencil, smem-staged coalesced interleaved output. ----
__global__ void __launch_bounds__(32*GPP, 3) k_last(int ssel,
                                                    float* __restrict__ out_ilv) {
    __shared__ float2 red0[GPP][32];
    __shared__ float2 sC[12][32];
    __shared__ float  smo[64*49];

    int tx = threadIdx.x;
    int ty = threadIdx.y;
    int c0 = ty * CPT;
    int tid = ty * 32 + tx;

    int h  = blockIdx.x >> 3;
    int wbase = (blockIdx.x & 7) << 6;
    int w  = wbase + 2 * tx;
    int hm = (h - 1) & 511, hp = (h + 1) & 511;
    int b0 = h << 9, bm = hm << 9, bp = hp << 9;
    int wm1 = (w - 1) & 511;
    int wp2 = (w + 2) & 511;
    int pA = b0 + w;

    const float* x  = (ssel == 1) ? (const float*)g_a : (const float*)g_b;
    const float* si = (ssel == 1) ? (const float*)g_s0 : (const float*)g_s1;

    stage_coeffs(sC, b0, wbase, tid);

    float2 s2  = *(const float2*)&si[pA];
    float2 sp2 = *(const float2*)&si[bp + w];
    float2 sr2 = *(const float2*)&si[b0 + wp2];
    float dsxA = sp2.x - s2.x, dsxB = sp2.y - s2.y;
    float dsyA = s2.y  - s2.x, dsyB = sr2.x - s2.y;
    __syncthreads();

    float2 C[12];
    #pragma unroll
    for (int k = 0; k < 12; k++)
        C[k] = sC[k][tx];

    float2 val[CPT];
    float2 cen[CPT];
    float vsumA = 0.0f, vsumB = 0.0f;
    #pragma unroll
    for (int c = 0; c < CPT; c++) {
        const float* xc = x + (size_t)(c0 + c) * NP;
        float  Lm = xc[bm + wm1], Rm = xc[bm + wp2];
        float2 Mm = *(const float2*)&xc[bm + w];
        float  L0 = xc[b0 + wm1], R0 = xc[b0 + wp2];
        float2 M0 = *(const float2*)&xc[b0 + w];
        float  Lp = xc[bp + wm1], Rp = xc[bp + wp2];
        float2 Mp = *(const float2*)&xc[bp + w];

        float accA = C[4].x * M0.x;
        accA = fmaf(C[0].x, Lm,   accA);
        accA = fmaf(C[1].x, Mm.x, accA);
        accA = fmaf(C[2].x, Mm.y, accA);
        accA = fmaf(C[3].x, L0,   accA);
        accA = fmaf(C[5].x, M0.y, accA);
        accA = fmaf(C[6].x, Lp,   accA);
        accA = fmaf(C[7].x, Mp.x, accA);
        accA = fmaf(C[8].x, Mp.y, accA);
        float vxA = (Mp.x - M0.x) - dsxA;
        float vyA = (M0.y - M0.x) - dsyA;
        accA = fmaf(fmaf(C[11].x, vyA, C[9].x * vxA), vxA, accA);
        accA = fmaf(C[10].x, vyA * vyA, accA);
        accA = fmaf(0.1f, M0.x, accA);

        float accB = C[4].y * M0.y;
        accB = fmaf(C[0].y, Mm.x, accB);
        accB = fmaf(C[1].y, Mm.y, accB);
        accB = fmaf(C[2].y, Rm,   accB);
        accB = fmaf(C[3].y, M0.x, accB);
        accB = fmaf(C[5].y, R0,   accB);
        accB = fmaf(C[6].y, Mp.x, accB);
        accB = fmaf(C[7].y, Mp.y, accB);
        accB = fmaf(C[8].y, Rp,   accB);
        float vxB = (Mp.y - M0.y) - dsxB;
        float vyB = (R0   - M0.y) - dsyB;
        accB = fmaf(fmaf(C[11].y, vyB, C[9].y * vxB), vxB, accB);
        accB = fmaf(C[10].y, vyB * vyB, accB);
        accB = fmaf(0.1f, M0.y, accB);

        val[c].x = accA; val[c].y = accB;
        cen[c] = M0;
        vsumA += accA; vsumB += accB;
    }

    red0[ty][tx].x = vsumA;
    red0[ty][tx].y = vsumB;
    __syncthreads();
    float meanA = 0.0f, meanB = 0.0f;
    #pragma unroll
    for (int g = 0; g < GPP; g++) {
        meanA += red0[g][tx].x;
        meanB += red0[g][tx].y;
    }
    meanA *= (1.0f / 48.0f);
    meanB *= (1.0f / 48.0f);

    int pxA = 2 * tx, pxB = 2 * tx + 1;
    #pragma unroll
    for (int c = 0; c < CPT; c++) {
        float tA = val[c].x - meanA;
        float tB = val[c].y - meanB;
        tA = fminf(fmaxf(tA, -1e8f), 1e8f);
        tB = fminf(fmaxf(tB, -1e8f), 1e8f);
        smo[pxA*49 + c0 + c] = fmaf(0.2f, tA, cen[c].x);
        smo[pxB*49 + c0 + c] = fmaf(0.2f, tB, cen[c].y);
    }
    __syncthreads();

    float4* o4 = (float4*)(out_ilv + (size_t)blockIdx.x * 64 * NC);
    #pragma unroll
    for (int i = 0; i < 3; i++) {
        int f4 = i * 256 + tid;
        int off = f4 * 4;
        int px = off / 48;
        int ch = off % 48;
        const float* s4 = &smo[px*49 + ch];
        float4 t;
        t.x = s4[0]; t.y = s4[1]; t.z = s4[2]; t.w = s4[3];
        o4[f4] = t;
    }
}

extern "C" void kernel_launch(void* const* d_in, const int* in_sizes, int n_in,
                              void* d_out, int out_size) {
    const float* v    = (const float*)d_in[0];
    const float* Dt   = (const float*)d_in[1];
    const float* dg   = (const float*)d_in[2];
    const float* hinv = (const float*)d_in[3];
    float* out = (float*)d_out;

    k_init<<<NP / 64, 256>>>(v, Dt, dg, hinv);

    dim3 blk(32, GPP);
    int grid = NP / PXW;   // 4096
    k_step<<<grid, blk>>>(1);
    k_step<<<grid, blk>>>(2);
    k_step<<<grid, blk>>>(1);
    k_step<<<grid, blk>>>(2);
    k_last<<<grid, blk>>>(1, out);
}

// round 15
// speedup vs baseline: 1.4241x; 1.0341x over previous
#include <cuda_runtime.h>

#define HH 512
#define WW 512
#define NC 48
#define NP (HH*WW)
#define CPT 6    // channels per thread
#define GPP 8    // channel-groups (warps) per pixel strip
#define PXW 64   // pixels per block (32 lanes x 2 px/thread)

// ---- scratch (static device globals: allocation-free, graph-safe) ----
__device__ float g_a[NC*NP];
__device__ float g_b[NC*NP];
__device__ float g_s0[NP];
__device__ float g_s1[NP];
__device__ float g_aux[12*NP];   // 12 planar scalar coeff planes (A4 has +MSQ folded)

// ---- K0: fused init. Per 64-px block: coalesced transpose v -> planar g_a
//          + s0 = logsumexp, and (threads 0-63) stencil-weight precompute. ----
__global__ void __launch_bounds__(256) k_init(const float* __restrict__ v,
                                              const float* __restrict__ Dt,
                                              const float* __restrict__ dg,
                                              const float* __restrict__ hinv) {
    __shared__ float sm[64*49];
    __shared__ float red[4][64];
    int tid = threadIdx.x;
    int p0 = blockIdx.x * 64;

    const float4* src = (const float4*)v + (size_t)blockIdx.x * 768;
    #pragma unroll
    for (int i = 0; i < 3; i++) {
        int f4 = i * 256 + tid;
        float4 t = src[f4];
        int off = f4 * 4;
        int px = off / 48;
        int ch = off % 48;
        float* d = &sm[px*49 + ch];
        d[0] = t.x; d[1] = t.y; d[2] = t.z; d[3] = t.w;
    }

    if (tid < 64) {
        int p = p0 + tid;
        int h = p >> 9, w = p & 511;
        int hm = (h - 1) & 511, hp = (h + 1) & 511;
        int wm = (w - 1) & 511, wp = (w + 1) & 511;
        #define DTA(hh,ww) Dt[(((hh)<<9)+(ww))*3+0]
        #define DTC(hh,ww) Dt[(((hh)<<9)+(ww))*3+1]
        #define DTB(hh,ww) Dt[(((hh)<<9)+(ww))*3+2]
        float a00 = DTA(h,w),  c00 = DTC(h,w),  b00 = DTB(h,w);
        float a_hm = DTA(hm,w), b_hm = DTB(hm,w);
        float a_hp = DTA(hp,w), b_hp = DTB(hp,w);
        float c_wm = DTC(h,wm), b_wm = DTB(h,wm);
        float c_wp = DTC(h,wp), b_wp = DTB(h,wp);
        float b_mm = DTB(hm,wm);
        float b_mp = DTB(hm,wp);
        float b_pm = DTB(hp,wm);
        float b_pp = DTB(hp,wp);
        #undef DTA
        #undef DTC
        #undef DTB
        float A0 = (fabsf(b_pm) - b_pm + fabsf(b00) - b00) * 0.25f;
        float A1 = (c_wm + c00 - fabsf(b_wm) - fabsf(b00)) * 0.5f;
        float A2 = (fabsf(b_mm) + b_mm + fabsf(b00) + b00) * 0.25f;
        float A3 = (a_hp + a00 - fabsf(b_hp) - fabsf(b00)) * 0.5f;
        float A4 = -(a_hp + 2.0f*a00 + a_hm) * 0.5f
                   - (fabsf(b_pm) - b_pm + fabsf(b_mm) + b_mm) * 0.25f
                   - (fabsf(b_pp) + b_pp + fabsf(b_mp) - b_mp) * 0.25f
                   + (fabsf(b_hp) + fabsf(b_hm) + fabsf(b_wp) + fabsf(b_wm) + 2.0f*fabsf(b00)) * 0.5f
                   - (c_wp + 2.0f*c00 + c_wm) * 0.5f;
        float A5 = (a_hm + a00 - fabsf(b_hm) - fabsf(b00)) * 0.5f;
        float A6 = (fabsf(b_pp) + b_pp + fabsf(b00) + b00) * 0.25f;
        float A7 = (c_wp + c00 - fabsf(b_wp) - fabsf(b00)) * 0.5f;
        float A8 = (fabsf(b_mp) - b_mp + fabsf(b00) - b00) * 0.25f;

        float inv_dg = 1.0f / dg[p];
        float mhm = (h > 0)      ? 1.0f : 0.0f;
        float mhp = (h < HH - 1) ? 1.0f : 0.0f;
        float mwm = (w > 0)      ? 1.0f : 0.0f;
        float mwp = (w < WW - 1) ? 1.0f : 0.0f;

        g_aux[0*NP+p]  = A0 * inv_dg * mhm * mwm;
        g_aux[1*NP+p]  = A1 * inv_dg * mhm;
        g_aux[2*NP+p]  = A2 * inv_dg * mhm * mwp;
        g_aux[3*NP+p]  = A3 * inv_dg * mwm;
        g_aux[4*NP+p]  = A4 * inv_dg + 0.1f;       // MSQ folded into center tap
        g_aux[5*NP+p]  = A5 * inv_dg * mwp;
        g_aux[6*NP+p]  = A6 * inv_dg * mhp * mwm;
        g_aux[7*NP+p]  = A7 * inv_dg * mhp;
        g_aux[8*NP+p]  = A8 * inv_dg * mhp * mwp;
        g_aux[9*NP+p]  = 0.5f * hinv[p*3+0];
        g_aux[10*NP+p] = 0.5f * hinv[p*3+1];
        g_aux[11*NP+p] =        hinv[p*3+2];
    }
    __syncthreads();

    int px = tid & 63;
    int cg = tid >> 6;
    int p  = p0 + px;
    float vv[12];
    float m = -3.402823466e38f;
    #pragma unroll
    for (int j = 0; j < 12; j++) {
        vv[j] = sm[px*49 + cg*12 + j];
        m = fmaxf(m, vv[j]);
        g_a[(size_t)(cg*12 + j)*NP + p] = vv[j];
    }
    red[cg][px] = m;
    __syncthreads();
    m = fmaxf(fmaxf(red[0][px], red[1][px]), fmaxf(red[2][px], red[3][px]));
    float es = 0.0f;
    #pragma unroll
    for (int j = 0; j < 12; j++) es += __expf(vv[j] - m);
    __syncthreads();
    red[cg][px] = es;
    __syncthreads();
    if (cg == 0) {
        float sum = red[0][px] + red[1][px] + red[2][px] + red[3][px];
        g_s0[p] = m + __logf(sum);
    }
}

// ---- K2: fused Euler step (steps 1..4); 2 horiz px x 6 ch per thread.
//          Exact R12 hot loop (best measured: 40.1us). ----
__global__ void __launch_bounds__(32*GPP, 3) k_step(int ssel) {
    __shared__ float2 red0[GPP][32];
    __shared__ float2 red1[GPP][32];
    __shared__ float2 red2[GPP][32];

    int tx = threadIdx.x;
    int ty = threadIdx.y;
    int c0 = ty * CPT;

    int h  = blockIdx.x >> 3;
    int w  = ((blockIdx.x & 7) << 6) + 2 * tx;
    int hm = (h - 1) & 511, hp = (h + 1) & 511;
    int b0 = h << 9, bm = hm << 9, bp = hp << 9;
    int wm1 = (w - 1) & 511;
    int wp2 = (w + 2) & 511;
    int pA = b0 + w;

    const float* x  = (ssel == 1) ? (const float*)g_a : (const float*)g_b;
    float* xo       = (ssel == 1) ? g_b : g_a;
    const float* si = (ssel == 1) ? (const float*)g_s0 : (const float*)g_s1;
    float* so       = (ssel == 1) ? g_s1 : g_s0;

    float2 C[12];
    #pragma unroll
    for (int k = 0; k < 12; k++)
        C[k] = *(const float2*)&g_aux[k*NP + pA];

    float2 s2  = *(const float2*)&si[pA];
    float2 sp2 = *(const float2*)&si[bp + w];
    float2 sr2 = *(const float2*)&si[b0 + wp2];
    float dsxA = sp2.x - s2.x, dsxB = sp2.y - s2.y;
    float dsyA = s2.y  - s2.x, dsyB = sr2.x - s2.y;

    float2 val[CPT];
    float2 cen[CPT];
    float vsumA = 0.0f, vsumB = 0.0f;
    #pragma unroll
    for (int c = 0; c < CPT; c++) {
        const float* xc = x + (size_t)(c0 + c) * NP;
        float  Lm = xc[bm + wm1], Rm = xc[bm + wp2];
        float2 Mm = *(const float2*)&xc[bm + w];
        float  L0 = xc[b0 + wm1], R0 = xc[b0 + wp2];
        float2 M0 = *(const float2*)&xc[b0 + w];
        float  Lp = xc[bp + wm1], Rp = xc[bp + wp2];
        float2 Mp = *(const float2*)&xc[bp + w];

        float accA = C[4].x * M0.x;              // A4 includes +MSQ
        accA = fmaf(C[0].x, Lm,   accA);
        accA = fmaf(C[1].x, Mm.x, accA);
        accA = fmaf(C[2].x, Mm.y, accA);
        accA = fmaf(C[3].x, L0,   accA);
        accA = fmaf(C[5].x, M0.y, accA);
        accA = fmaf(C[6].x, Lp,   accA);
        accA = fmaf(C[7].x, Mp.x, accA);
        accA = fmaf(C[8].x, Mp.y, accA);
        float vxA = (Mp.x - M0.x) - dsxA;
        float vyA = (M0.y - M0.x) - dsyA;
        accA = fmaf(fmaf(C[11].x, vyA, C[9].x * vxA), vxA, accA);
        accA = fmaf(C[10].x, vyA * vyA, accA);

        float accB = C[4].y * M0.y;
        accB = fmaf(C[0].y, Mm.x, accB);
        accB = fmaf(C[1].y, Mm.y, accB);
        accB = fmaf(C[2].y, Rm,   accB);
        accB = fmaf(C[3].y, M0.x, accB);
        accB = fmaf(C[5].y, R0,   accB);
        accB = fmaf(C[6].y, Mp.x, accB);
        accB = fmaf(C[7].y, Mp.y, accB);
        accB = fmaf(C[8].y, Rp,   accB);
        float vxB = (Mp.y - M0.y) - dsxB;
        float vyB = (R0   - M0.y) - dsyB;
        accB = fmaf(fmaf(C[11].y, vyB, C[9].y * vxB), vxB, accB);
        accB = fmaf(C[10].y, vyB * vyB, accB);

        val[c].x = accA; val[c].y = accB;
        cen[c] = M0;
        vsumA += accA; vsumB += accB;
    }

    red0[ty][tx].x = vsumA;
    red0[ty][tx].y = vsumB;
    __syncthreads();
    float meanA = 0.0f, meanB = 0.0f;
    #pragma unroll
    for (int g = 0; g < GPP; g++) {
        meanA += red0[g][tx].x;
        meanB += red0[g][tx].y;
    }
    meanA *= (1.0f / 48.0f);
    meanB *= (1.0f / 48.0f);

    #pragma unroll
    for (int c = 0; c < CPT; c++) {
        float tA = val[c].x - meanA;
        float tB = val[c].y - meanB;
        tA = fminf(fmaxf(tA, -1e8f), 1e8f);
        tB = fminf(fmaxf(tB, -1e8f), 1e8f);
        val[c].x = fmaf(0.2f, tA, cen[c].x);
        val[c].y = fmaf(0.2f, tB, cen[c].y);
    }

    float mA = val[0].x, mB = val[0].y;
    #pragma unroll
    for (int c = 1; c < CPT; c++) {
        mA = fmaxf(mA, val[c].x);
        mB = fmaxf(mB, val[c].y);
    }
    red1[ty][tx].x = mA;
    red1[ty][tx].y = mB;
    #pragma unroll
    for (int c = 0; c < CPT; c++)
        *(float2*)&xo[(size_t)(c0 + c) * NP + pA] = val[c];
    __syncthreads();
    mA = red1[0][tx].x; mB = red1[0][tx].y;
    #pragma unroll
    for (int g = 1; g < GPP; g++) {
        mA = fmaxf(mA, red1[g][tx].x);
        mB = fmaxf(mB, red1[g][tx].y);
    }
    float esA = 0.0f, esB = 0.0f;
    #pragma unroll
    for (int c = 0; c < CPT; c++) {
        esA += __expf(val[c].x - mA);
        esB += __expf(val[c].y - mB);
    }
    red2[ty][tx].x = esA;
    red2[ty][tx].y = esB;
    __syncthreads();
    if (ty == 0) {
        float sumA = 0.0f, sumB = 0.0f;
        #pragma unroll
        for (int g = 0; g < GPP; g++) {
            sumA += red2[g][tx].x;
            sumB += red2[g][tx].y;
        }
        float2 os;
        os.x = mA + __logf(sumA);
        os.y = mB + __logf(sumB);
        *(float2*)&so[pA] = os;
    }
}

// ---- K3: final step — same stencil, smem-staged coalesced interleaved output. ----
__global__ void __launch_bounds__(32*GPP, 3) k_last(int ssel,
                                                    float* __restrict__ out_ilv) {
    __shared__ float2 red0[GPP][32];
    __shared__ float  smo[64*49];

    int tx = threadIdx.x;
    int ty = threadIdx.y;
    int c0 = ty * CPT;

    int h  = blockIdx.x >> 3;
    int w  = ((blockIdx.x & 7) << 6) + 2 * tx;
    int hm = (h - 1) & 511, hp = (h + 1) & 511;
    int b0 = h << 9, bm = hm << 9, bp = hp << 9;
    int wm1 = (w - 1) & 511;
    int wp2 = (w + 2) & 511;
    int pA = b0 + w;

    const float* x  = (ssel == 1) ? (const float*)g_a : (const float*)g_b;
    const float* si = (ssel == 1) ? (const float*)g_s0 : (const float*)g_s1;

    float2 C[12];
    #pragma unroll
    for (int k = 0; k < 12; k++)
        C[k] = *(const float2*)&g_aux[k*NP + pA];

    float2 s2  = *(const float2*)&si[pA];
    float2 sp2 = *(const float2*)&si[bp + w];
    float2 sr2 = *(const float2*)&si[b0 + wp2];
    float dsxA = sp2.x - s2.x, dsxB = sp2.y - s2.y;
    float dsyA = s2.y  - s2.x, dsyB = sr2.x - s2.y;

    float2 val[CPT];
    float2 cen[CPT];
    float vsumA = 0.0f, vsumB = 0.0f;
    #pragma unroll
    for (int c = 0; c < CPT; c++) {
        const float* xc = x + (size_t)(c0 + c) * NP;
        float  Lm = xc[bm + wm1], Rm = xc[bm + wp2];
        float2 Mm = *(const float2*)&xc[bm + w];
        float  L0 = xc[b0 + wm1], R0 = xc[b0 + wp2];
        float2 M0 = *(const float2*)&xc[b0 + w];
        float  Lp = xc[bp + wm1], Rp = xc[bp + wp2];
        float2 Mp = *(const float2*)&xc[bp + w];

        float accA = C[4].x * M0.x;
        accA = fmaf(C[0].x, Lm,   accA);
        accA = fmaf(C[1].x, Mm.x, accA);
        accA = fmaf(C[2].x, Mm.y, accA);
        accA = fmaf(C[3].x, L0,   accA);
        accA = fmaf(C[5].x, M0.y, accA);
        accA = fmaf(C[6].x, Lp,   accA);
        accA = fmaf(C[7].x, Mp.x, accA);
        accA = fmaf(C[8].x, Mp.y, accA);
        float vxA = (Mp.x - M0.x) - dsxA;
        float vyA = (M0.y - M0.x) - dsyA;
        accA = fmaf(fmaf(C[11].x, vyA, C[9].x * vxA), vxA, accA);
        accA = fmaf(C[10].x, vyA * vyA, accA);

        float accB = C[4].y * M0.y;
        accB = fmaf(C[0].y, Mm.x, accB);
        accB = fmaf(C[1].y, Mm.y, accB);
        accB = fmaf(C[2].y, Rm,   accB);
        accB = fmaf(C[3].y, M0.x, accB);
        accB = fmaf(C[5].y, R0,   accB);
        accB = fmaf(C[6].y, Mp.x, accB);
        accB = fmaf(C[7].y, Mp.y, accB);
        accB = fmaf(C[8].y, Rp,   accB);
        float vxB = (Mp.y - M0.y) - dsxB;
        float vyB = (R0   - M0.y) - dsyB;
        accB = fmaf(fmaf(C[11].y, vyB, C[9].y * vxB), vxB, accB);
        accB = fmaf(C[10].y, vyB * vyB, accB);

        val[c].x = accA; val[c].y = accB;
        cen[c] = M0;
        vsumA += accA; vsumB += accB;
    }

    red0[ty][tx].x = vsumA;
    red0[ty][tx].y = vsumB;
    __syncthreads();
    float meanA = 0.0f, meanB = 0.0f;
    #pragma unroll
    for (int g = 0; g < GPP; g++) {
        meanA += red0[g][tx].x;
        meanB += red0[g][tx].y;
    }
    meanA *= (1.0f / 48.0f);
    meanB *= (1.0f / 48.0f);

    int pxA = 2 * tx, pxB = 2 * tx + 1;
    #pragma unroll
    for (int c = 0; c < CPT; c++) {
        float tA = val[c].x - meanA;
        float tB = val[c].y - meanB;
        tA = fminf(fmaxf(tA, -1e8f), 1e8f);
        tB = fminf(fmaxf(tB, -1e8f), 1e8f);
        smo[pxA*49 + c0 + c] = fmaf(0.2f, tA, cen[c].x);
        smo[pxB*49 + c0 + c] = fmaf(0.2f, tB, cen[c].y);
    }
    __syncthreads();

    int tid = ty * 32 + tx;
    float4* o4 = (float4*)(out_ilv + (size_t)blockIdx.x * 64 * NC);
    #pragma unroll
    for (int i = 0; i < 3; i++) {
        int f4 = i * 256 + tid;
        int off = f4 * 4;
        int px = off / 48;
        int ch = off % 48;
        const float* s4 = &smo[px*49 + ch];
        float4 t;
        t.x = s4[0]; t.y = s4[1]; t.z = s4[2]; t.w = s4[3];
        __stcs(&o4[f4], t);   // streaming store: output never re-read
    }
}

extern "C" void kernel_launch(void* const* d_in, const int* in_sizes, int n_in,
                              void* d_out, int out_size) {
    const float* v    = (const float*)d_in[0];
    const float* Dt   = (const float*)d_in[1];
    const float* dg   = (const float*)d_in[2];
    const float* hinv = (const float*)d_in[3];
    float* out = (float*)d_out;

    k_init<<<NP / 64, 256>>>(v, Dt, dg, hinv);

    dim3 blk(32, GPP);
    int grid = NP / PXW;   // 4096
    k_step<<<grid, blk>>>(1);
    k_step<<<grid, blk>>>(2);
    k_step<<<grid, blk>>>(1);
    k_step<<<grid, blk>>>(2);
    k_last<<<grid, blk>>>(1, out);
}

// round 17
// speedup vs baseline: 1.4846x; 1.0425x over previous
#include <cuda_runtime.h>

#define HH 512
#define WW 512
#define NC 48
#define NP (HH*WW)
#define CPT 6    // channels per thread
#define GPP 8    // channel-groups (warps) per pixel strip
#define PXW 64   // pixels per block (32 lanes x 2 px/thread)

// ---- scratch (static device globals: allocation-free, graph-safe) ----
__device__ float g_a[NC*NP];
__device__ float g_b[NC*NP];
__device__ float g_s0[NP];
__device__ float g_s1[NP];
__device__ float g_aux[12*NP];   // 12 planar scalar coeff planes (A4 has +MSQ folded)

// ---- K0: fused init. Per 64-px block: coalesced transpose v -> planar g_a
//          + s0 = logsumexp, and (threads 0-63) stencil-weight precompute. ----
__global__ void __launch_bounds__(256) k_init(const float* __restrict__ v,
                                              const float* __restrict__ Dt,
                                              const float* __restrict__ dg,
                                              const float* __restrict__ hinv) {
    __shared__ float sm[64*49];
    __shared__ float red[4][64];
    int tid = threadIdx.x;
    int p0 = blockIdx.x * 64;

    const float4* src = (const float4*)v + (size_t)blockIdx.x * 768;
    #pragma unroll
    for (int i = 0; i < 3; i++) {
        int f4 = i * 256 + tid;
        float4 t = src[f4];
        int off = f4 * 4;
        int px = off / 48;
        int ch = off % 48;
        float* d = &sm[px*49 + ch];
        d[0] = t.x; d[1] = t.y; d[2] = t.z; d[3] = t.w;
    }

    if (tid < 64) {
        int p = p0 + tid;
        int h = p >> 9, w = p & 511;
        int hm = (h - 1) & 511, hp = (h + 1) & 511;
        int wm = (w - 1) & 511, wp = (w + 1) & 511;
        #define DTA(hh,ww) Dt[(((hh)<<9)+(ww))*3+0]
        #define DTC(hh,ww) Dt[(((hh)<<9)+(ww))*3+1]
        #define DTB(hh,ww) Dt[(((hh)<<9)+(ww))*3+2]
        float a00 = DTA(h,w),  c00 = DTC(h,w),  b00 = DTB(h,w);
        float a_hm = DTA(hm,w), b_hm = DTB(hm,w);
        float a_hp = DTA(hp,w), b_hp = DTB(hp,w);
        float c_wm = DTC(h,wm), b_wm = DTB(h,wm);
        float c_wp = DTC(h,wp), b_wp = DTB(h,wp);
        float b_mm = DTB(hm,wm);
        float b_mp = DTB(hm,wp);
        float b_pm = DTB(hp,wm);
        float b_pp = DTB(hp,wp);
        #undef DTA
        #undef DTC
        #undef DTB
        float A0 = (fabsf(b_pm) - b_pm + fabsf(b00) - b00) * 0.25f;
        float A1 = (c_wm + c00 - fabsf(b_wm) - fabsf(b00)) * 0.5f;
        float A2 = (fabsf(b_mm) + b_mm + fabsf(b00) + b00) * 0.25f;
        float A3 = (a_hp + a00 - fabsf(b_hp) - fabsf(b00)) * 0.5f;
        float A4 = -(a_hp + 2.0f*a00 + a_hm) * 0.5f
                   - (fabsf(b_pm) - b_pm + fabsf(b_mm) + b_mm) * 0.25f
                   - (fabsf(b_pp) + b_pp + fabsf(b_mp) - b_mp) * 0.25f
                   + (fabsf(b_hp) + fabsf(b_hm) + fabsf(b_wp) + fabsf(b_wm) + 2.0f*fabsf(b00)) * 0.5f
                   - (c_wp + 2.0f*c00 + c_wm) * 0.5f;
        float A5 = (a_hm + a00 - fabsf(b_hm) - fabsf(b00)) * 0.5f;
        float A6 = (fabsf(b_pp) + b_pp + fabsf(b00) + b00) * 0.25f;
        float A7 = (c_wp + c00 - fabsf(b_wp) - fabsf(b00)) * 0.5f;
        float A8 = (fabsf(b_mp) - b_mp + fabsf(b00) - b00) * 0.25f;

        float inv_dg = 1.0f / dg[p];
        float mhm = (h > 0)      ? 1.0f : 0.0f;
        float mhp = (h < HH - 1) ? 1.0f : 0.0f;
        float mwm = (w > 0)      ? 1.0f : 0.0f;
        float mwp = (w < WW - 1) ? 1.0f : 0.0f;

        g_aux[0*NP+p]  = A0 * inv_dg * mhm * mwm;
        g_aux[1*NP+p]  = A1 * inv_dg * mhm;
        g_aux[2*NP+p]  = A2 * inv_dg * mhm * mwp;
        g_aux[3*NP+p]  = A3 * inv_dg * mwm;
        g_aux[4*NP+p]  = A4 * inv_dg + 0.1f;       // MSQ folded into center tap
        g_aux[5*NP+p]  = A5 * inv_dg * mwp;
        g_aux[6*NP+p]  = A6 * inv_dg * mhp * mwm;
        g_aux[7*NP+p]  = A7 * inv_dg * mhp;
        g_aux[8*NP+p]  = A8 * inv_dg * mhp * mwp;
        g_aux[9*NP+p]  = 0.5f * hinv[p*3+0];
        g_aux[10*NP+p] = 0.5f * hinv[p*3+1];
        g_aux[11*NP+p] =        hinv[p*3+2];
    }
    __syncthreads();

    int px = tid & 63;
    int cg = tid >> 6;
    int p  = p0 + px;
    float vv[12];
    float m = -3.402823466e38f;
    #pragma unroll
    for (int j = 0; j < 12; j++) {
        vv[j] = sm[px*49 + cg*12 + j];
        m = fmaxf(m, vv[j]);
        g_a[(size_t)(cg*12 + j)*NP + p] = vv[j];
    }
    red[cg][px] = m;
    __syncthreads();
    m = fmaxf(fmaxf(red[0][px], red[1][px]), fmaxf(red[2][px], red[3][px]));
    float es = 0.0f;
    #pragma unroll
    for (int j = 0; j < 12; j++) es += __expf(vv[j] - m);
    __syncthreads();
    red[cg][px] = es;
    __syncthreads();
    if (cg == 0) {
        float sum = red[0][px] + red[1][px] + red[2][px] + red[3][px];
        g_s0[p] = m + __logf(sum);
    }
}

// ---- K2: fused Euler step (steps 1..4); 2 horiz px x 6 ch per thread.
//          R12 hot loop; single-sync hierarchical logsumexp epilogue. ----
__global__ void __launch_bounds__(32*GPP, 3) k_step(int ssel) {
    __shared__ float2 red0[GPP][32];
    __shared__ float2 red1[GPP][32];   // local max per ty
    __shared__ float2 red2[GPP][32];   // local expsum per ty

    int tx = threadIdx.x;
    int ty = threadIdx.y;
    int c0 = ty * CPT;

    int h  = blockIdx.x >> 3;
    int w  = ((blockIdx.x & 7) << 6) + 2 * tx;
    int hm = (h - 1) & 511, hp = (h + 1) & 511;
    int b0 = h << 9, bm = hm << 9, bp = hp << 9;
    int wm1 = (w - 1) & 511;
    int wp2 = (w + 2) & 511;
    int pA = b0 + w;

    const float* x  = (ssel == 1) ? (const float*)g_a : (const float*)g_b;
    float* xo       = (ssel == 1) ? g_b : g_a;
    const float* si = (ssel == 1) ? (const float*)g_s0 : (const float*)g_s1;
    float* so       = (ssel == 1) ? g_s1 : g_s0;

    float2 C[12];
    #pragma unroll
    for (int k = 0; k < 12; k++)
        C[k] = *(const float2*)&g_aux[k*NP + pA];

    float2 s2  = *(const float2*)&si[pA];
    float2 sp2 = *(const float2*)&si[bp + w];
    float2 sr2 = *(const float2*)&si[b0 + wp2];
    float dsxA = sp2.x - s2.x, dsxB = sp2.y - s2.y;
    float dsyA = s2.y  - s2.x, dsyB = sr2.x - s2.y;

    float2 val[CPT];
    float2 cen[CPT];
    float vsumA = 0.0f, vsumB = 0.0f;
    #pragma unroll
    for (int c = 0; c < CPT; c++) {
        const float* xc = x + (size_t)(c0 + c) * NP;
        float  Lm = xc[bm + wm1], Rm = xc[bm + wp2];
        float2 Mm = *(const float2*)&xc[bm + w];
        float  L0 = xc[b0 + wm1], R0 = xc[b0 + wp2];
        float2 M0 = *(const float2*)&xc[b0 + w];
        float  Lp = xc[bp + wm1], Rp = xc[bp + wp2];
        float2 Mp = *(const float2*)&xc[bp + w];

        float accA = C[4].x * M0.x;              // A4 includes +MSQ
        accA = fmaf(C[0].x, Lm,   accA);
        accA = fmaf(C[1].x, Mm.x, accA);
        accA = fmaf(C[2].x, Mm.y, accA);
        accA = fmaf(C[3].x, L0,   accA);
        accA = fmaf(C[5].x, M0.y, accA);
        accA = fmaf(C[6].x, Lp,   accA);
        accA = fmaf(C[7].x, Mp.x, accA);
        accA = fmaf(C[8].x, Mp.y, accA);
        float vxA = (Mp.x - M0.x) - dsxA;
        float vyA = (M0.y - M0.x) - dsyA;
        accA = fmaf(fmaf(C[11].x, vyA, C[9].x * vxA), vxA, accA);
        accA = fmaf(C[10].x, vyA * vyA, accA);

        float accB = C[4].y * M0.y;
        accB = fmaf(C[0].y, Mm.x, accB);
        accB = fmaf(C[1].y, Mm.y, accB);
        accB = fmaf(C[2].y, Rm,   accB);
        accB = fmaf(C[3].y, M0.x, accB);
        accB = fmaf(C[5].y, R0,   accB);
        accB = fmaf(C[6].y, Mp.x, accB);
        accB = fmaf(C[7].y, Mp.y, accB);
        accB = fmaf(C[8].y, Rp,   accB);
        float vxB = (Mp.y - M0.y) - dsxB;
        float vyB = (R0   - M0.y) - dsyB;
        accB = fmaf(fmaf(C[11].y, vyB, C[9].y * vxB), vxB, accB);
        accB = fmaf(C[10].y, vyB * vyB, accB);

        val[c].x = accA; val[c].y = accB;
        cen[c] = M0;
        vsumA += accA; vsumB += accB;
    }

    red0[ty][tx].x = vsumA;
    red0[ty][tx].y = vsumB;
    __syncthreads();
    float meanA = 0.0f, meanB = 0.0f;
    #pragma unroll
    for (int g = 0; g < GPP; g++) {
        meanA += red0[g][tx].x;
        meanB += red0[g][tx].y;
    }
    meanA *= (1.0f / 48.0f);
    meanB *= (1.0f / 48.0f);

    #pragma unroll
    for (int c = 0; c < CPT; c++) {
        float tA = val[c].x - meanA;
        float tB = val[c].y - meanB;
        tA = fminf(fmaxf(tA, -1e8f), 1e8f);
        tB = fminf(fmaxf(tB, -1e8f), 1e8f);
        val[c].x = fmaf(0.2f, tA, cen[c].x);
        val[c].y = fmaf(0.2f, tB, cen[c].y);
    }

    // hierarchical logsumexp: local max + local expsum BEFORE the (single) sync
    float mA = val[0].x, mB = val[0].y;
    #pragma unroll
    for (int c = 1; c < CPT; c++) {
        mA = fmaxf(mA, val[c].x);
        mB = fmaxf(mB, val[c].y);
    }
    float esA = 0.0f, esB = 0.0f;
    #pragma unroll
    for (int c = 0; c < CPT; c++) {
        esA += __expf(val[c].x - mA);
        esB += __expf(val[c].y - mB);
    }
    red1[ty][tx].x = mA;
    red1[ty][tx].y = mB;
    red2[ty][tx].x = esA;
    red2[ty][tx].y = esB;
    #pragma unroll
    for (int c = 0; c < CPT; c++)
        *(float2*)&xo[(size_t)(c0 + c) * NP + pA] = val[c];
    __syncthreads();
    if (ty == 0) {
        float gmA = red1[0][tx].x, gmB = red1[0][tx].y;
        #pragma unroll
        for (int g = 1; g < GPP; g++) {
            gmA = fmaxf(gmA, red1[g][tx].x);
            gmB = fmaxf(gmB, red1[g][tx].y);
        }
        float sumA = 0.0f, sumB = 0.0f;
        #pragma unroll
        for (int g = 0; g < GPP; g++) {
            sumA += red2[g][tx].x * __expf(red1[g][tx].x - gmA);
            sumB += red2[g][tx].y * __expf(red1[g][tx].y - gmB);
        }
        float2 os;
        os.x = gmA + __logf(sumA);
        os.y = gmB + __logf(sumB);
        *(float2*)&so[pA] = os;
    }
}

// ---- K3: final step — same stencil, smem-staged coalesced interleaved output. ----
__global__ void __launch_bounds__(32*GPP, 3) k_last(int ssel,
                                                    float* __restrict__ out_ilv) {
    __shared__ float2 red0[GPP][32];
    __shared__ float  smo[64*49];

    int tx = threadIdx.x;
    int ty = threadIdx.y;
    int c0 = ty * CPT;

    int h  = blockIdx.x >> 3;
    int w  = ((blockIdx.x & 7) << 6) + 2 * tx;
    int hm = (h - 1) & 511, hp = (h + 1) & 511;
    int b0 = h << 9, bm = hm << 9, bp = hp << 9;
    int wm1 = (w - 1) & 511;
    int wp2 = (w + 2) & 511;
    int pA = b0 + w;

    const float* x  = (ssel == 1) ? (const float*)g_a : (const float*)g_b;
    const float* si = (ssel == 1) ? (const float*)g_s0 : (const float*)g_s1;

    float2 C[12];
    #pragma unroll
    for (int k = 0; k < 12; k++)
        C[k] = *(const float2*)&g_aux[k*NP + pA];

    float2 s2  = *(const float2*)&si[pA];
    float2 sp2 = *(const float2*)&si[bp + w];
    float2 sr2 = *(const float2*)&si[b0 + wp2];
    float dsxA = sp2.x - s2.x, dsxB = sp2.y - s2.y;
    float dsyA = s2.y  - s2.x, dsyB = sr2.x - s2.y;

    float2 val[CPT];
    float2 cen[CPT];
    float vsumA = 0.0f, vsumB = 0.0f;
    #pragma unroll
    for (int c = 0; c < CPT; c++) {
        const float* xc = x + (size_t)(c0 + c) * NP;
        float  Lm = xc[bm + wm1], Rm = xc[bm + wp2];
        float2 Mm = *(const float2*)&xc[bm + w];
        float  L0 = xc[b0 + wm1], R0 = xc[b0 + wp2];
        float2 M0 = *(const float2*)&xc[b0 + w];
        float  Lp = xc[bp + wm1], Rp = xc[bp + wp2];
        float2 Mp = *(const float2*)&xc[bp + w];

        float accA = C[4].x * M0.x;
        accA = fmaf(C[0].x, Lm,   accA);
        accA = fmaf(C[1].x, Mm.x, accA);
        accA = fmaf(C[2].x, Mm.y, accA);
        accA = fmaf(C[3].x, L0,   accA);
        accA = fmaf(C[5].x, M0.y, accA);
        accA = fmaf(C[6].x, Lp,   accA);
        accA = fmaf(C[7].x, Mp.x, accA);
        accA = fmaf(C[8].x, Mp.y, accA);
        float vxA = (Mp.x - M0.x) - dsxA;
        float vyA = (M0.y - M0.x) - dsyA;
        accA = fmaf(fmaf(C[11].x, vyA, C[9].x * vxA), vxA, accA);
        accA = fmaf(C[10].x, vyA * vyA, accA);

        float accB = C[4].y * M0.y;
        accB = fmaf(C[0].y, Mm.x, accB);
        accB = fmaf(C[1].y, Mm.y, accB);
        accB = fmaf(C[2].y, Rm,   accB);
        accB = fmaf(C[3].y, M0.x, accB);
        accB = fmaf(C[5].y, R0,   accB);
        accB = fmaf(C[6].y, Mp.x, accB);
        accB = fmaf(C[7].y, Mp.y, accB);
        accB = fmaf(C[8].y, Rp,   accB);
        float vxB = (Mp.y - M0.y) - dsxB;
        float vyB = (R0   - M0.y) - dsyB;
        accB = fmaf(fmaf(C[11].y, vyB, C[9].y * vxB), vxB, accB);
        accB = fmaf(C[10].y, vyB * vyB, accB);

        val[c].x = accA; val[c].y = accB;
        cen[c] = M0;
        vsumA += accA; vsumB += accB;
    }

    red0[ty][tx].x = vsumA;
    red0[ty][tx].y = vsumB;
    __syncthreads();
    float meanA = 0.0f, meanB = 0.0f;
    #pragma unroll
    for (int g = 0; g < GPP; g++) {
        meanA += red0[g][tx].x;
        meanB += red0[g][tx].y;
    }
    meanA *= (1.0f / 48.0f);
    meanB *= (1.0f / 48.0f);

    int pxA = 2 * tx, pxB = 2 * tx + 1;
    #pragma unroll
    for (int c = 0; c < CPT; c++) {
        float tA = val[c].x - meanA;
        float tB = val[c].y - meanB;
        tA = fminf(fmaxf(tA, -1e8f), 1e8f);
        tB = fminf(fmaxf(tB, -1e8f), 1e8f);
        smo[pxA*49 + c0 + c] = fmaf(0.2f, tA, cen[c].x);
        smo[pxB*49 + c0 + c] = fmaf(0.2f, tB, cen[c].y);
    }
    __syncthreads();

    int tid = ty * 32 + tx;
    float4* o4 = (float4*)(out_ilv + (size_t)blockIdx.x * 64 * NC);
    #pragma unroll
    for (int i = 0; i < 3; i++) {
        int f4 = i * 256 + tid;
        int off = f4 * 4;
        int px = off / 48;
        int ch = off % 48;
        const float* s4 = &smo[px*49 + ch];
        float4 t;
        t.x = s4[0]; t.y = s4[1]; t.z = s4[2]; t.w = s4[3];
        __stcs(&o4[f4], t);   // streaming store: output never re-read
    }
}

extern "C" void kernel_launch(void* const* d_in, const int* in_sizes, int n_in,
                              void* d_out, int out_size) {
    const float* v    = (const float*)d_in[0];
    const float* Dt   = (const float*)d_in[1];
    const float* dg   = (const float*)d_in[2];
    const float* hinv = (const float*)d_in[3];
    float* out = (float*)d_out;

    k_init<<<NP / 64, 256>>>(v, Dt, dg, hinv);

    dim3 blk(32, GPP);
    int grid = NP / PXW;   // 4096
    k_step<<<grid, blk>>>(1);
    k_step<<<grid, blk>>>(2);
    k_step<<<grid, blk>>>(1);
    k_step<<<grid, blk>>>(2);
    k_last<<<grid, blk>>>(1, out);
}